// round 7
// baseline (speedup 1.0000x reference)
#include <cuda_runtime.h>
#include <cstdint>

// DivEncLayer via mma.sync.m16n8k8 tf32 + cp.async staging.
// out[b,q] = W2_q . ELU(x[b, q*128:(q+1)*128] @ W1_q + b1_q) + b2_q
// B=2048, Q=128, S=128(K), H=32(N).
// Block = (q, 64-batch tile), 128 threads, 4096 blocks, 4 CTAs/SM.

#define B_TOT 2048
#define Q_TOT 128
#define S_DIM 128
#define H_DIM 32
#define C_TOT 16384
#define BT    64
#define XSTRIDE 132   // floats per row; bank(4g+c) all-distinct for fragment loads

// smem floats: sx[64*132] | swt[32*132] | sb1[32] | sw2[32]
#define SX_F   (BT * XSTRIDE)          // 8448
#define SWT_F  (H_DIM * XSTRIDE)       // 4224
#define SMEM_F (SX_F + SWT_F + 64)
#define SMEM_BYTES (SMEM_F * 4)        // 50944

__device__ __forceinline__ float to_tf32(float x) {
    uint32_t r;
    asm("cvt.rna.tf32.f32 %0, %1;" : "=r"(r) : "f"(x));
    return __uint_as_float(r);
}

__device__ __forceinline__ uint32_t smem_u32(const void* p) {
    uint32_t a;
    asm("{ .reg .u64 t; cvta.to.shared.u64 t, %1; cvt.u32.u64 %0, t; }" : "=r"(a) : "l"(p));
    return a;
}

__device__ __forceinline__ void cp_async16(uint32_t dst, const void* src) {
    asm volatile("cp.async.ca.shared.global [%0], [%1], 16;" :: "r"(dst), "l"(src));
}

__device__ __forceinline__ void mma_tf32(float* d, const uint32_t* a, const uint32_t* b) {
    asm volatile(
        "mma.sync.aligned.m16n8k8.row.col.f32.tf32.tf32.f32 "
        "{%0,%1,%2,%3}, {%4,%5,%6,%7}, {%8,%9}, {%0,%1,%2,%3};"
        : "+f"(d[0]), "+f"(d[1]), "+f"(d[2]), "+f"(d[3])
        : "r"(a[0]), "r"(a[1]), "r"(a[2]), "r"(a[3]), "r"(b[0]), "r"(b[1]));
}

__device__ __forceinline__ float elu_f(float v) {
    return v > 0.0f ? v : (__expf(v) - 1.0f);
}

extern __shared__ float smem[];

__global__ void __launch_bounds__(128, 4)
divenc_mma_kernel(const float* __restrict__ xg,
                  const float* __restrict__ w1g,
                  const float* __restrict__ b1g,
                  const float* __restrict__ w2g,
                  const float* __restrict__ b2g,
                  float* __restrict__ out)
{
    float* sx  = smem;               // [m][k], stride 132
    float* swt = smem + SX_F;        // [h][k], stride 132 (W1 transposed, tf32)
    float* sb1 = swt + SWT_F;        // [32]
    float* sw2 = sb1 + 32;           // [32]

    const int q  = blockIdx.x;
    const int bt = blockIdx.y;
    const int t  = threadIdx.x;

    // ---- stage x tile via cp.async (raw fp32; convert in-place later) ----
    {
        const char* xbase = (const char*)(xg + (size_t)bt * BT * C_TOT + (size_t)q * S_DIM);
        const uint32_t sx_u = smem_u32(sx);
        #pragma unroll
        for (int idx = t; idx < BT * (S_DIM / 4); idx += 128) {
            int row = idx >> 5;          // 0..63
            int c4  = idx & 31;          // float4 col
            cp_async16(sx_u + (uint32_t)(row * XSTRIDE + c4 * 4) * 4,
                       xbase + ((size_t)row * C_TOT + c4 * 4) * 4);
        }
        asm volatile("cp.async.commit_group;" ::: "memory");
    }

    // ---- stage W1^T (LDG under the async x loads), tf32-convert on store ----
    {
        const float4* wq4 = reinterpret_cast<const float4*>(w1g + (size_t)q * (S_DIM * H_DIM));
        #pragma unroll
        for (int idx = t; idx < (S_DIM * H_DIM) / 4; idx += 128) {
            int k  = idx >> 3;       // 0..127
            int h4 = idx & 7;        // h group
            float4 wv = wq4[idx];    // W1[k][4h4 .. 4h4+3]
            swt[(h4 * 4 + 0) * XSTRIDE + k] = to_tf32(wv.x);
            swt[(h4 * 4 + 1) * XSTRIDE + k] = to_tf32(wv.y);
            swt[(h4 * 4 + 2) * XSTRIDE + k] = to_tf32(wv.z);
            swt[(h4 * 4 + 3) * XSTRIDE + k] = to_tf32(wv.w);
        }
    }
    if (t < 32) {
        sb1[t] = b1g[q * H_DIM + t];
        sw2[t] = w2g[q * H_DIM + t];
    }

    asm volatile("cp.async.wait_group 0;" ::: "memory");
    __syncthreads();

    // ---- in-place tf32 RNA conversion of x tile ----
    #pragma unroll
    for (int idx = t; idx < BT * (S_DIM / 4); idx += 128) {
        int row = idx >> 5;
        int c4  = idx & 31;
        float4* p = reinterpret_cast<float4*>(&sx[row * XSTRIDE + c4 * 4]);
        float4 v = *p;
        v.x = to_tf32(v.x); v.y = to_tf32(v.y);
        v.z = to_tf32(v.z); v.w = to_tf32(v.w);
        *p = v;
    }
    __syncthreads();

    // ---- per-warp tile: M=16 rows, N=32 (4 n-tiles of 8), K=128 ----
    const int w = t >> 5;     // 0..3
    const int l = t & 31;
    const int g = l >> 2;     // 0..7
    const int c = l & 3;      // 0..3
    const int m0 = w * 16;

    float acc[4][4];
    #pragma unroll
    for (int j = 0; j < 4; j++)
        #pragma unroll
        for (int i = 0; i < 4; i++) acc[j][i] = 0.0f;

    const uint32_t* sxu  = reinterpret_cast<const uint32_t*>(sx);
    const uint32_t* swtu = reinterpret_cast<const uint32_t*>(swt);
    const int arow0 = (m0 + g) * XSTRIDE + c;       // A row g
    const int arow1 = (m0 + g + 8) * XSTRIDE + c;   // A row g+8

    #pragma unroll 4
    for (int s = 0; s < 16; s++) {
        const int k0 = s * 8;
        uint32_t a[4];
        a[0] = sxu[arow0 + k0];
        a[1] = sxu[arow1 + k0];
        a[2] = sxu[arow0 + k0 + 4];
        a[3] = sxu[arow1 + k0 + 4];
        #pragma unroll
        for (int j = 0; j < 4; j++) {
            uint32_t b[2];
            const int brow = (j * 8 + g) * XSTRIDE + k0 + c;
            b[0] = swtu[brow];
            b[1] = swtu[brow + 4];
            mma_tf32(acc[j], a, b);
        }
    }

    // ---- epilogue: thread owns rows {m0+g, m0+g+8}, cols {j*8+2c, j*8+2c+1} ----
    float sum0 = 0.0f, sum1 = 0.0f;
    #pragma unroll
    for (int j = 0; j < 4; j++) {
        const int col = j * 8 + c * 2;
        const float b1a = sb1[col],     w2a = sw2[col];
        const float b1b = sb1[col + 1], w2b = sw2[col + 1];
        sum0 = fmaf(elu_f(acc[j][0] + b1a), w2a, sum0);
        sum0 = fmaf(elu_f(acc[j][1] + b1b), w2b, sum0);
        sum1 = fmaf(elu_f(acc[j][2] + b1a), w2a, sum1);
        sum1 = fmaf(elu_f(acc[j][3] + b1b), w2b, sum1);
    }
    // reduce over the 4 lanes of the quad (lane%4)
    sum0 += __shfl_xor_sync(0xffffffffu, sum0, 1);
    sum0 += __shfl_xor_sync(0xffffffffu, sum0, 2);
    sum1 += __shfl_xor_sync(0xffffffffu, sum1, 1);
    sum1 += __shfl_xor_sync(0xffffffffu, sum1, 2);

    if (c == 0) {
        const float b2q = b2g[q];
        const int b0 = bt * BT + m0 + g;
        out[(size_t)b0 * Q_TOT + q]       = sum0 + b2q;
        out[(size_t)(b0 + 8) * Q_TOT + q] = sum1 + b2q;
    }
}

extern "C" void kernel_launch(void* const* d_in, const int* in_sizes, int n_in,
                              void* d_out, int out_size)
{
    const float* x  = (const float*)d_in[0];
    const float* w1 = (const float*)d_in[1];
    const float* b1 = (const float*)d_in[2];
    const float* w2 = (const float*)d_in[3];
    const float* b2 = (const float*)d_in[4];
    float* out = (float*)d_out;

    cudaFuncSetAttribute(divenc_mma_kernel,
                         cudaFuncAttributeMaxDynamicSharedMemorySize, SMEM_BYTES);

    dim3 grid(Q_TOT, B_TOT / BT);   // (128, 32)
    divenc_mma_kernel<<<grid, 128, SMEM_BYTES>>>(x, w1, b1, w2, b2, out);
}

// round 9
// speedup vs baseline: 1.4489x; 1.4489x over previous
#include <cuda_runtime.h>
#include <cstdint>

// DivEncLayer via mma.sync.m16n8k8 tf32, pipelined staging:
// x tile staged as 4 cp.async quarters, each tracked by an mbarrier
// (init 256, cp.async.mbarrier.arrive.NOINC from all 256 threads);
// warp pair i starts its MMA as soon as quarter i lands.
// out[b,q] = W2_q . ELU(x[b, q*128:(q+1)*128] @ W1_q + b1_q) + b2_q
// B=2048, Q=128, S=128(K), H=32(N). Block=(q, 128-batch tile), 256 thr, 2048 blocks.

#define B_TOT 2048
#define Q_TOT 128
#define S_DIM 128
#define H_DIM 32
#define C_TOT 16384
#define BT    128
#define XSTRIDE 132   // floats per row; bank(4g+c) all-distinct for fragment loads

// smem floats: sx[128*132] | swt[32*132] | sb1[32] | sw2[32] | mbar[4 u64]
#define SX_F   (BT * XSTRIDE)          // 16896
#define SWT_F  (H_DIM * XSTRIDE)       // 4224
#define SMEM_F (SX_F + SWT_F + 32 + 32 + 16)
#define SMEM_BYTES (SMEM_F * 4)        // ~84.8 KB -> 2 CTAs/SM

__device__ __forceinline__ float to_tf32(float x) {
    uint32_t r;
    asm("cvt.rna.tf32.f32 %0, %1;" : "=r"(r) : "f"(x));
    return __uint_as_float(r);
}
__device__ __forceinline__ uint32_t to_tf32_u(float x) {
    uint32_t r;
    asm("cvt.rna.tf32.f32 %0, %1;" : "=r"(r) : "f"(x));
    return r;
}
__device__ __forceinline__ uint32_t smem_u32(const void* p) {
    uint32_t a;
    asm("{ .reg .u64 t; cvta.to.shared.u64 t, %1; cvt.u32.u64 %0, t; }" : "=r"(a) : "l"(p));
    return a;
}
__device__ __forceinline__ void cp_async16(uint32_t dst, const void* src) {
    asm volatile("cp.async.ca.shared.global [%0], [%1], 16;" :: "r"(dst), "l"(src));
}
#define MBARRIER_INIT(mb, cnt) \
    asm volatile("mbarrier.init.shared.b64 [%0], %1;" :: "r"(mb), "r"(cnt) : "memory")
// .noinc: arrive DECREMENTS against the init count (default form would first
// increment pending, netting zero -> deadlock; that was the R8 hang).
#define CPASYNC_MBAR_ARRIVE_NOINC(mb) \
    asm volatile("cp.async.mbarrier.arrive.noinc.shared.b64 [%0];" :: "r"(mb) : "memory")
#define MBARRIER_WAIT(mb, ph) do { \
    asm volatile("{\n\t.reg .pred P1;\n\tWL_%=:\n\t" \
        "mbarrier.try_wait.parity.shared.b64 P1, [%0], %1;\n\t" \
        "@P1 bra.uni WD_%=;\n\tbra.uni WL_%=;\n\tWD_%=:\n\t}" \
        :: "r"(mb), "r"(ph) : "memory"); \
} while (0)

__device__ __forceinline__ void mma_tf32(float* d, const uint32_t* a, const uint32_t* b) {
    asm volatile(
        "mma.sync.aligned.m16n8k8.row.col.f32.tf32.tf32.f32 "
        "{%0,%1,%2,%3}, {%4,%5,%6,%7}, {%8,%9}, {%0,%1,%2,%3};"
        : "+f"(d[0]), "+f"(d[1]), "+f"(d[2]), "+f"(d[3])
        : "r"(a[0]), "r"(a[1]), "r"(a[2]), "r"(a[3]), "r"(b[0]), "r"(b[1]));
}
__device__ __forceinline__ float elu_f(float v) {
    return v > 0.0f ? v : (__expf(v) - 1.0f);
}

extern __shared__ float smem[];

__global__ void __launch_bounds__(256, 2)
divenc_pipe_kernel(const float* __restrict__ xg,
                   const float* __restrict__ w1g,
                   const float* __restrict__ b1g,
                   const float* __restrict__ w2g,
                   const float* __restrict__ b2g,
                   float* __restrict__ out)
{
    float* sx  = smem;               // [m][k] raw fp32, stride 132
    float* swt = smem + SX_F;        // [h][k] tf32, stride 132
    float* sb1 = swt + SWT_F;        // [32]
    float* sw2 = sb1 + 32;           // [32]
    float* mbf = sw2 + 32;           // 4 mbarriers (u64 each)

    const int q  = blockIdx.x;
    const int bt = blockIdx.y;
    const int t  = threadIdx.x;
    const uint32_t mb_base = smem_u32(mbf);

    // ---- init mbarriers: each expects 256 (noinc) arrivals ----
    if (t < 4) MBARRIER_INIT(mb_base + t * 8, 256);
    __syncthreads();

    // ---- issue x quarters: 4 x (32 rows = 1024 float4), each + noinc arrive ----
    {
        const uint32_t sx_u = smem_u32(sx);
        const float* xrowbase = xg + (size_t)bt * BT * C_TOT + (size_t)q * S_DIM;
        #pragma unroll
        for (int qt = 0; qt < 4; qt++) {
            #pragma unroll
            for (int j = 0; j < 4; j++) {
                int u   = t + 256 * j;       // 0..1023
                int row = qt * 32 + (u >> 5);
                int c4  = u & 31;
                cp_async16(sx_u + (uint32_t)(row * XSTRIDE + c4 * 4) * 4,
                           xrowbase + (size_t)row * C_TOT + c4 * 4);
            }
            // arrive fires when THIS thread's prior cp.asyncs (quarters 0..qt) complete
            CPASYNC_MBAR_ARRIVE_NOINC(mb_base + qt * 8);
        }
    }

    // ---- stage W1^T (LDG overlaps the x stream), tf32-convert once ----
    {
        const float4* wq4 = reinterpret_cast<const float4*>(w1g + (size_t)q * (S_DIM * H_DIM));
        #pragma unroll
        for (int idx = t; idx < (S_DIM * H_DIM) / 4; idx += 256) {
            int k  = idx >> 3;
            int h4 = idx & 7;
            float4 wv = wq4[idx];
            swt[(h4 * 4 + 0) * XSTRIDE + k] = to_tf32(wv.x);
            swt[(h4 * 4 + 1) * XSTRIDE + k] = to_tf32(wv.y);
            swt[(h4 * 4 + 2) * XSTRIDE + k] = to_tf32(wv.z);
            swt[(h4 * 4 + 3) * XSTRIDE + k] = to_tf32(wv.w);
        }
    }
    if (t < 32) {
        sb1[t] = b1g[q * H_DIM + t];
        sw2[t] = w2g[q * H_DIM + t];
    }
    __syncthreads();   // swt/sb1/sw2 visible to all warps (x handled by mbarriers)

    // ---- per-warp tile: M=16 rows, N=32, K=128 ----
    const int w = t >> 5;
    const int l = t & 31;
    const int g = l >> 2;
    const int c = l & 3;
    const int m0 = w * 16;

    // wait only for this warp pair's x quarter
    MBARRIER_WAIT(mb_base + (w >> 1) * 8, 0);

    float acc[4][4];
    #pragma unroll
    for (int j = 0; j < 4; j++)
        #pragma unroll
        for (int i = 0; i < 4; i++) acc[j][i] = 0.0f;

    const float*    sxf  = sx;
    const uint32_t* swtu = reinterpret_cast<const uint32_t*>(swt);
    const int arow0 = (m0 + g) * XSTRIDE + c;
    const int arow1 = (m0 + g + 8) * XSTRIDE + c;

    #pragma unroll 4
    for (int s = 0; s < 16; s++) {
        const int k0 = s * 8;
        uint32_t a[4];
        a[0] = to_tf32_u(sxf[arow0 + k0]);
        a[1] = to_tf32_u(sxf[arow1 + k0]);
        a[2] = to_tf32_u(sxf[arow0 + k0 + 4]);
        a[3] = to_tf32_u(sxf[arow1 + k0 + 4]);
        #pragma unroll
        for (int j = 0; j < 4; j++) {
            uint32_t b[2];
            const int brow = (j * 8 + g) * XSTRIDE + k0 + c;
            b[0] = swtu[brow];
            b[1] = swtu[brow + 4];
            mma_tf32(acc[j], a, b);
        }
    }

    // ---- epilogue ----
    float sum0 = 0.0f, sum1 = 0.0f;
    #pragma unroll
    for (int j = 0; j < 4; j++) {
        const int col = j * 8 + c * 2;
        const float b1a = sb1[col],     w2a = sw2[col];
        const float b1b = sb1[col + 1], w2b = sw2[col + 1];
        sum0 = fmaf(elu_f(acc[j][0] + b1a), w2a, sum0);
        sum0 = fmaf(elu_f(acc[j][1] + b1b), w2b, sum0);
        sum1 = fmaf(elu_f(acc[j][2] + b1a), w2a, sum1);
        sum1 = fmaf(elu_f(acc[j][3] + b1b), w2b, sum1);
    }
    sum0 += __shfl_xor_sync(0xffffffffu, sum0, 1);
    sum0 += __shfl_xor_sync(0xffffffffu, sum0, 2);
    sum1 += __shfl_xor_sync(0xffffffffu, sum1, 1);
    sum1 += __shfl_xor_sync(0xffffffffu, sum1, 2);

    if (c == 0) {
        const float b2q = b2g[q];
        const int b0 = bt * BT + m0 + g;
        out[(size_t)b0 * Q_TOT + q]       = sum0 + b2q;
        out[(size_t)(b0 + 8) * Q_TOT + q] = sum1 + b2q;
    }
}

extern "C" void kernel_launch(void* const* d_in, const int* in_sizes, int n_in,
                              void* d_out, int out_size)
{
    const float* x  = (const float*)d_in[0];
    const float* w1 = (const float*)d_in[1];
    const float* b1 = (const float*)d_in[2];
    const float* w2 = (const float*)d_in[3];
    const float* b2 = (const float*)d_in[4];
    float* out = (float*)d_out;

    cudaFuncSetAttribute(divenc_pipe_kernel,
                         cudaFuncAttributeMaxDynamicSharedMemorySize, SMEM_BYTES);

    dim3 grid(Q_TOT, B_TOT / BT);   // (128, 16)
    divenc_pipe_kernel<<<grid, 256, SMEM_BYTES>>>(x, w1, b1, w2, b2, out);
}